// round 1
// baseline (speedup 1.0000x reference)
#include <cuda_runtime.h>
#include <cuda_bf16.h>
#include <math.h>

// Problem constants (from metadata / reference)
#define Bb 4
#define Tt 1024
#define Cc 1024
#define Hh 16
#define HKV 4
#define Dd 64
#define ROWS (Bb*Tt)          // 4096 tokens
#define QDIM (Hh*Dd)          // 1024
#define KVDIM (HKV*Dd)        // 256
#define GATE_CH 12

// Scratch (statically allocated; no cudaMalloc allowed)
__device__ float g_Q[ROWS * QDIM];    // 16 MB
__device__ float g_K[ROWS * KVDIM];   // 4 MB
__device__ float g_V[ROWS * KVDIM];   // 4 MB
__device__ float g_Y[ROWS * QDIM];    // 16 MB

// ---------------------------------------------------------------------------
// GEMM: C[M,N] = A[M,K] * B[N,K]^T   (both A and B are K-major, row-major)
// BM=BN=128, BK=16, 256 threads, 8x8 register microtile per thread.
// smem tiles stored transposed ([k][m]) so compute-phase reads are LDS.128
// along m/n with no padding needed.
// ---------------------------------------------------------------------------
#define BM 128
#define BN 128
#define BK 16

__global__ __launch_bounds__(256) void gemm_nt(
    const float* __restrict__ A, const float* __restrict__ B,
    float* __restrict__ C, int M, int N, int K)
{
    __shared__ float As[BK][BM];
    __shared__ float Bs[BK][BN];

    const int tid = threadIdx.x;
    const int tx = tid & 15;       // 0..15 -> N direction
    const int ty = tid >> 4;       // 0..15 -> M direction

    const float* Ab = A + (size_t)blockIdx.y * BM * K;
    const float* Bb_ = B + (size_t)blockIdx.x * BN * K;

    float acc[8][8];
#pragma unroll
    for (int i = 0; i < 8; i++)
#pragma unroll
        for (int j = 0; j < 8; j++) acc[i][j] = 0.f;

    for (int k0 = 0; k0 < K; k0 += BK) {
        // 128 rows x 16 k = 512 float4 per operand; 2 per thread
#pragma unroll
        for (int it = 0; it < 2; it++) {
            int idx = tid + it * 256;          // 0..511
            int row = idx >> 2;                // 0..127
            int k4  = (idx & 3) << 2;          // 0,4,8,12
            float4 va = *(const float4*)(Ab + (size_t)row * K + k0 + k4);
            As[k4 + 0][row] = va.x; As[k4 + 1][row] = va.y;
            As[k4 + 2][row] = va.z; As[k4 + 3][row] = va.w;
            float4 vb = *(const float4*)(Bb_ + (size_t)row * K + k0 + k4);
            Bs[k4 + 0][row] = vb.x; Bs[k4 + 1][row] = vb.y;
            Bs[k4 + 2][row] = vb.z; Bs[k4 + 3][row] = vb.w;
        }
        __syncthreads();

#pragma unroll
        for (int kk = 0; kk < BK; kk++) {
            float a[8], b[8];
            *(float4*)(a + 0) = *(const float4*)&As[kk][ty * 8 + 0];
            *(float4*)(a + 4) = *(const float4*)&As[kk][ty * 8 + 4];
            *(float4*)(b + 0) = *(const float4*)&Bs[kk][tx * 8 + 0];
            *(float4*)(b + 4) = *(const float4*)&Bs[kk][tx * 8 + 4];
#pragma unroll
            for (int i = 0; i < 8; i++)
#pragma unroll
                for (int j = 0; j < 8; j++)
                    acc[i][j] = fmaf(a[i], b[j], acc[i][j]);
        }
        __syncthreads();
    }

#pragma unroll
    for (int i = 0; i < 8; i++) {
        size_t row = (size_t)blockIdx.y * BM + ty * 8 + i;
        float* Cr = C + row * N + blockIdx.x * BN + tx * 8;
        *(float4*)(Cr + 0) = *(const float4*)&acc[i][0];
        *(float4*)(Cr + 4) = *(const float4*)&acc[i][4];
    }
}

// ---------------------------------------------------------------------------
// Postproc: per-token gate+V update, RoPE + RMS-norm on Q and K.
// One CTA (256 threads = 8 warps) per token row.
// ---------------------------------------------------------------------------
__global__ __launch_bounds__(256) void postproc(
    const float* __restrict__ x, const float* __restrict__ ve,
    const float* __restrict__ cosb, const float* __restrict__ sinb,
    const float* __restrict__ Wg)
{
    const int row = blockIdx.x;          // 0..4095
    const int t = row & (Tt - 1);
    const int warp = threadIdx.x >> 5;
    const int lane = threadIdx.x & 31;

    // --- V gating: warps 0..3 handle kv-head g = warp ---
    if (warp < HKV) {
        float p = 0.f;
        if (lane < GATE_CH)
            p = x[(size_t)row * Cc + lane] * Wg[warp * GATE_CH + lane];
#pragma unroll
        for (int o = 16; o > 0; o >>= 1)
            p += __shfl_xor_sync(0xffffffffu, p, o);
        float gate = 3.f / (1.f + __expf(-p));
        size_t base = (size_t)row * KVDIM + warp * Dd;
        g_V[base + lane]      += gate * ve[base + lane];
        g_V[base + 32 + lane] += gate * ve[base + 32 + lane];
    }

    // --- RoPE + RMS-norm: 16 Q heads + 4 K heads = 20 tasks over 8 warps ---
    const float cv = cosb[t * 32 + lane];
    const float sv = sinb[t * 32 + lane];
    for (int tsk = warp; tsk < Hh + HKV; tsk += 8) {
        float* ptr = (tsk < Hh)
            ? (g_Q + (size_t)row * QDIM + tsk * Dd)
            : (g_K + (size_t)row * KVDIM + (tsk - Hh) * Dd);
        float x1 = ptr[lane];
        float x2 = ptr[lane + 32];
        float y1 = x1 * cv + x2 * sv;
        float y2 = x2 * cv - x1 * sv;
        float ss = y1 * y1 + y2 * y2;
#pragma unroll
        for (int o = 16; o > 0; o >>= 1)
            ss += __shfl_xor_sync(0xffffffffu, ss, o);
        float sc = 1.2f * rsqrtf(ss * (1.0f / Dd) + 1.1920929e-7f);
        ptr[lane]      = y1 * sc;
        ptr[lane + 32] = y2 * sc;
    }
}

// ---------------------------------------------------------------------------
// Windowed causal attention, GQA rep=4. One CTA (64 threads) per
// (b, head, 64-query tile); one thread per query, streaming softmax over
// 64-key chunks. Score buffer uses skewed indexing (no pad) to stay at 48KB.
// ---------------------------------------------------------------------------
__global__ __launch_bounds__(64) void attn(
    const int* __restrict__ wptr)
{
    __shared__ float Ks[64][64];
    __shared__ float Vs[64][64];
    __shared__ float Ss[64][64];   // skewed: Ss[i][(j+i)&63]

    const int qt = blockIdx.x;     // 0..15
    const int h  = blockIdx.y;     // 0..15
    const int b  = blockIdx.z;     // 0..3
    const int g  = h >> 2;         // kv head
    const int tid = threadIdx.x;   // 0..63 = query within tile

    const int q0 = qt * 64;
    const int i  = q0 + tid;       // global query pos in [0,T)
    const size_t qrow = (size_t)(b * Tt + i) * QDIM + h * Dd;

    float q[64];
#pragma unroll
    for (int c4 = 0; c4 < 64; c4 += 4)
        *(float4*)&q[c4] = *(const float4*)&g_Q[qrow + c4];

    float acc[64];
#pragma unroll
    for (int c = 0; c < 64; c++) acc[c] = 0.f;
    float m = -1e30f, l = 0.f;

    const int w = wptr[0];
    int jmin = q0 - w; if (jmin < 0) jmin = 0;

    for (int c0 = (jmin >> 6) << 6; c0 <= q0; c0 += 64) {
        // load K,V chunk (coalesced float4)
#pragma unroll
        for (int it = 0; it < 16; it++) {
            int idx = it * 64 + tid;           // float4 index 0..1023
            int r  = idx >> 4;
            int c4 = (idx & 15) << 2;
            size_t src = (size_t)(b * Tt + c0 + r) * KVDIM + g * Dd + c4;
            *(float4*)&Ks[r][c4] = *(const float4*)&g_K[src];
            *(float4*)&Vs[r][c4] = *(const float4*)&g_V[src];
        }
        __syncthreads();

        // pass 1: scores + chunk max
        float cmax = -1e30f;
        for (int j = 0; j < 64; j++) {
            int jg = c0 + j;
            float s = -1e30f;
            if (jg <= i && (i - jg) <= w) {
                float s0 = 0.f, s1 = 0.f, s2 = 0.f, s3 = 0.f;
#pragma unroll
                for (int c = 0; c < 64; c += 4) {
                    s0 = fmaf(q[c + 0], Ks[j][c + 0], s0);
                    s1 = fmaf(q[c + 1], Ks[j][c + 1], s1);
                    s2 = fmaf(q[c + 2], Ks[j][c + 2], s2);
                    s3 = fmaf(q[c + 3], Ks[j][c + 3], s3);
                }
                s = (s0 + s1 + s2 + s3) * 0.125f;
            }
            Ss[tid][(j + tid) & 63] = s;
            cmax = fmaxf(cmax, s);
        }

        // rescale running state
        float m_new = fmaxf(m, cmax);
        float resc = __expf(m - m_new);
        l *= resc;
#pragma unroll
        for (int c = 0; c < 64; c++) acc[c] *= resc;

        // pass 2: exp + PV accumulate
        for (int j = 0; j < 64; j++) {
            float p = __expf(Ss[tid][(j + tid) & 63] - m_new);
            l += p;
#pragma unroll
            for (int c = 0; c < 64; c++)
                acc[c] = fmaf(p, Vs[j][c], acc[c]);
        }
        m = m_new;
        __syncthreads();
    }

    float inv = 1.f / l;
    float* yr = g_Y + qrow;
#pragma unroll
    for (int c4 = 0; c4 < 64; c4 += 4) {
        float4 o;
        o.x = acc[c4 + 0] * inv; o.y = acc[c4 + 1] * inv;
        o.z = acc[c4 + 2] * inv; o.w = acc[c4 + 3] * inv;
        *(float4*)&yr[c4] = o;
    }
}

// ---------------------------------------------------------------------------
extern "C" void kernel_launch(void* const* d_in, const int* in_sizes, int n_in,
                              void* d_out, int out_size)
{
    const float* x   = (const float*)d_in[0];
    const float* ve  = (const float*)d_in[1];
    const float* cosb = (const float*)d_in[2];
    const float* sinb = (const float*)d_in[3];
    const float* Wq  = (const float*)d_in[4];
    const float* Wk  = (const float*)d_in[5];
    const float* Wv  = (const float*)d_in[6];
    const float* Wo  = (const float*)d_in[7];
    const float* Wg  = (const float*)d_in[8];
    const int*   win = (const int*)d_in[9];

    float* out = (float*)d_out;

    float* Qp; cudaGetSymbolAddress((void**)&Qp, g_Q);
    float* Kp; cudaGetSymbolAddress((void**)&Kp, g_K);
    float* Vp; cudaGetSymbolAddress((void**)&Vp, g_V);
    float* Yp; cudaGetSymbolAddress((void**)&Yp, g_Y);

    // QKV projections
    gemm_nt<<<dim3(QDIM / BN, ROWS / BM), 256>>>(x, Wq, Qp, ROWS, QDIM, Cc);
    gemm_nt<<<dim3(KVDIM / BN, ROWS / BM), 256>>>(x, Wk, Kp, ROWS, KVDIM, Cc);
    gemm_nt<<<dim3(KVDIM / BN, ROWS / BM), 256>>>(x, Wv, Vp, ROWS, KVDIM, Cc);

    // gate + RoPE + RMS-norm
    postproc<<<ROWS, 256>>>(x, ve, cosb, sinb, Wg);

    // windowed attention
    attn<<<dim3(Tt / 64, Hh, Bb), 64>>>(win);

    // output projection
    gemm_nt<<<dim3(QDIM / BN, ROWS / BM), 256>>>(Yp, Wo, out, ROWS, QDIM, Cc);
}

// round 3
// speedup vs baseline: 1.7124x; 1.7124x over previous
#include <cuda_runtime.h>
#include <cuda_bf16.h>
#include <math.h>
#include <cstdint>

// Problem constants
#define Bb 4
#define Tt 1024
#define Cc 1024
#define Hh 16
#define HKV 4
#define Dd 64
#define ROWS (Bb*Tt)          // 4096 tokens
#define QDIM (Hh*Dd)          // 1024
#define KVDIM (HKV*Dd)        // 256
#define GATE_CH 12

// Scratch (no cudaMalloc allowed)
__device__ float g_Q[ROWS * QDIM];    // 16 MB
__device__ float g_K[ROWS * KVDIM];   // 4 MB
__device__ float g_V[ROWS * KVDIM];   // 4 MB
__device__ float g_Y[ROWS * QDIM];    // 16 MB

__device__ __forceinline__ float tf32r(float x) {
    float y;
    asm("cvt.rna.tf32.f32 %0, %1;" : "=f"(y) : "f"(x));
    return y;
}

__device__ __forceinline__ void mma_tf32(float* d,
                                         const uint32_t* a, const uint32_t* b) {
    asm volatile(
        "mma.sync.aligned.m16n8k8.row.col.f32.tf32.tf32.f32 "
        "{%0,%1,%2,%3}, {%4,%5,%6,%7}, {%8,%9}, {%0,%1,%2,%3};"
        : "+f"(d[0]), "+f"(d[1]), "+f"(d[2]), "+f"(d[3])
        : "r"(a[0]), "r"(a[1]), "r"(a[2]), "r"(a[3]),
          "r"(b[0]), "r"(b[1]));
}

// ---------------------------------------------------------------------------
// tf32 mma.sync GEMM:  C[M,N] = A[M,K] * B[N,K]^T  (A, B row-major K-major)
// BM=BN=128, BK=32, 256 threads (8 warps, 4x2 M/N layout), warp tile 32x64.
// ---------------------------------------------------------------------------
#define BK 32
#define LDS_S (BK + 4)   // 36-word stride: fragment loads conflict-free

__global__ __launch_bounds__(256, 1) void gemm_tc(
    const float* __restrict__ A, const float* __restrict__ B,
    float* __restrict__ C, int M, int N, int K)
{
    __shared__ uint32_t As[128][LDS_S];
    __shared__ uint32_t Bs[128][LDS_S];

    const int tid = threadIdx.x;
    const int wid = tid >> 5;
    const int lane = tid & 31;
    const int warp_m = wid & 3;        // 0..3 -> 32-row slice
    const int warp_n = wid >> 2;       // 0..1 -> 64-col slice
    const int group = lane >> 2;       // 0..7
    const int kq = lane & 3;           // 0..3

    const float* Ab = A + (size_t)blockIdx.y * 128 * K;
    const float* Bp = B + (size_t)blockIdx.x * 128 * K;

    float acc[2][8][4];
#pragma unroll
    for (int mt = 0; mt < 2; mt++)
#pragma unroll
        for (int nt = 0; nt < 8; nt++)
#pragma unroll
            for (int c = 0; c < 4; c++) acc[mt][nt][c] = 0.f;

    const int nk = K >> 5;   // K/32 chunks

    // prefetch chunk 0
    float4 ra[4], rb[4];
#pragma unroll
    for (int t = 0; t < 4; t++) {
        int idx = tid + t * 256;            // 0..1023
        int row = idx >> 3;
        int c4  = (idx & 7) << 2;
        ra[t] = *(const float4*)(Ab + (size_t)row * K + c4);
        rb[t] = *(const float4*)(Bp + (size_t)row * K + c4);
    }

    for (int kc = 0; kc < nk; kc++) {
        if (kc > 0) __syncthreads();       // previous compute done
        // store chunk with RNA tf32 rounding
#pragma unroll
        for (int t = 0; t < 4; t++) {
            int idx = tid + t * 256;
            int row = idx >> 3;
            int c4  = (idx & 7) << 2;
            As[row][c4 + 0] = __float_as_uint(tf32r(ra[t].x));
            As[row][c4 + 1] = __float_as_uint(tf32r(ra[t].y));
            As[row][c4 + 2] = __float_as_uint(tf32r(ra[t].z));
            As[row][c4 + 3] = __float_as_uint(tf32r(ra[t].w));
            Bs[row][c4 + 0] = __float_as_uint(tf32r(rb[t].x));
            Bs[row][c4 + 1] = __float_as_uint(tf32r(rb[t].y));
            Bs[row][c4 + 2] = __float_as_uint(tf32r(rb[t].z));
            Bs[row][c4 + 3] = __float_as_uint(tf32r(rb[t].w));
        }
        __syncthreads();

        // prefetch next chunk (LDG overlaps mma stream below)
        if (kc + 1 < nk) {
#pragma unroll
            for (int t = 0; t < 4; t++) {
                int idx = tid + t * 256;
                int row = idx >> 3;
                int c4  = (idx & 7) << 2;
                size_t off = (size_t)row * K + (kc + 1) * BK + c4;
                ra[t] = *(const float4*)(Ab + off);
                rb[t] = *(const float4*)(Bp + off);
            }
        }

        // compute: 4 k-steps of 8
#pragma unroll
        for (int ks = 0; ks < 4; ks++) {
            const int k0 = ks * 8;
            uint32_t af[2][4];
#pragma unroll
            for (int mt = 0; mt < 2; mt++) {
                int r = warp_m * 32 + mt * 16 + group;
                af[mt][0] = As[r][k0 + kq];
                af[mt][1] = As[r + 8][k0 + kq];
                af[mt][2] = As[r][k0 + kq + 4];
                af[mt][3] = As[r + 8][k0 + kq + 4];
            }
            uint32_t bf[8][2];
#pragma unroll
            for (int nt = 0; nt < 8; nt++) {
                int cn = warp_n * 64 + nt * 8 + group;
                bf[nt][0] = Bs[cn][k0 + kq];
                bf[nt][1] = Bs[cn][k0 + kq + 4];
            }
#pragma unroll
            for (int mt = 0; mt < 2; mt++)
#pragma unroll
                for (int nt = 0; nt < 8; nt++)
                    mma_tf32(acc[mt][nt], af[mt], bf[nt]);
        }
    }

    // epilogue
#pragma unroll
    for (int mt = 0; mt < 2; mt++) {
        int r = blockIdx.y * 128 + warp_m * 32 + mt * 16 + group;
#pragma unroll
        for (int nt = 0; nt < 8; nt++) {
            int cn = blockIdx.x * 128 + warp_n * 64 + nt * 8 + 2 * kq;
            float2 v0 = make_float2(acc[mt][nt][0], acc[mt][nt][1]);
            float2 v1 = make_float2(acc[mt][nt][2], acc[mt][nt][3]);
            *(float2*)(C + (size_t)r * N + cn) = v0;
            *(float2*)(C + (size_t)(r + 8) * N + cn) = v1;
        }
    }
}

// ---------------------------------------------------------------------------
// Postproc: per-token gate+V update, RoPE + RMS-norm on Q and K.
// ---------------------------------------------------------------------------
__global__ __launch_bounds__(256) void postproc(
    const float* __restrict__ x, const float* __restrict__ ve,
    const float* __restrict__ cosb, const float* __restrict__ sinb,
    const float* __restrict__ Wg)
{
    const int row = blockIdx.x;
    const int t = row & (Tt - 1);
    const int warp = threadIdx.x >> 5;
    const int lane = threadIdx.x & 31;

    if (warp < HKV) {
        float p = 0.f;
        if (lane < GATE_CH)
            p = x[(size_t)row * Cc + lane] * Wg[warp * GATE_CH + lane];
#pragma unroll
        for (int o = 16; o > 0; o >>= 1)
            p += __shfl_xor_sync(0xffffffffu, p, o);
        float gate = 3.f / (1.f + __expf(-p));
        size_t base = (size_t)row * KVDIM + warp * Dd;
        g_V[base + lane]      += gate * ve[base + lane];
        g_V[base + 32 + lane] += gate * ve[base + 32 + lane];
    }

    const float cv = cosb[t * 32 + lane];
    const float sv = sinb[t * 32 + lane];
    for (int tsk = warp; tsk < Hh + HKV; tsk += 8) {
        float* ptr = (tsk < Hh)
            ? (g_Q + (size_t)row * QDIM + tsk * Dd)
            : (g_K + (size_t)row * KVDIM + (tsk - Hh) * Dd);
        float x1 = ptr[lane];
        float x2 = ptr[lane + 32];
        float y1 = x1 * cv + x2 * sv;
        float y2 = x2 * cv - x1 * sv;
        float ss = y1 * y1 + y2 * y2;
#pragma unroll
        for (int o = 16; o > 0; o >>= 1)
            ss += __shfl_xor_sync(0xffffffffu, ss, o);
        float sc = 1.2f * rsqrtf(ss * (1.0f / Dd) + 1.1920929e-7f);
        ptr[lane]      = y1 * sc;
        ptr[lane + 32] = y2 * sc;
    }
}

// ---------------------------------------------------------------------------
// Windowed causal attention, GQA rep=4. 128 threads per CTA:
// 2 threads per query, each owning half of the D=64 dims (partner = lane^1).
// ---------------------------------------------------------------------------
__global__ __launch_bounds__(128) void attn(const int* __restrict__ wptr)
{
    __shared__ float Ks[64][64];
    __shared__ float Vs[64][64];
    __shared__ float Ss[64][64];   // skewed: Ss[i][(j+i)&63]

    const int qt = blockIdx.x;
    const int h  = blockIdx.y;
    const int b  = blockIdx.z;
    const int g  = h >> 2;
    const int tid = threadIdx.x;   // 0..127
    const int qi = tid >> 1;       // query within tile
    const int hf = tid & 1;        // which half of D

    const int q0 = qt * 64;
    const int i  = q0 + qi;
    const size_t qrow = (size_t)(b * Tt + i) * QDIM + h * Dd + hf * 32;

    float q[32];
#pragma unroll
    for (int c4 = 0; c4 < 32; c4 += 4)
        *(float4*)&q[c4] = *(const float4*)&g_Q[qrow + c4];

    float acc[32];
#pragma unroll
    for (int c = 0; c < 32; c++) acc[c] = 0.f;
    float m = -1e30f, l = 0.f;

    const int w = wptr[0];
    int jmin = q0 - w; if (jmin < 0) jmin = 0;

    for (int c0 = (jmin >> 6) << 6; c0 <= q0; c0 += 64) {
        // load K,V chunk (coalesced float4), 128 threads
#pragma unroll
        for (int it = 0; it < 8; it++) {
            int idx = it * 128 + tid;          // float4 index 0..1023
            int r  = idx >> 4;
            int c4 = (idx & 15) << 2;
            size_t src = (size_t)(b * Tt + c0 + r) * KVDIM + g * Dd + c4;
            *(float4*)&Ks[r][c4] = *(const float4*)&g_K[src];
            *(float4*)&Vs[r][c4] = *(const float4*)&g_V[src];
        }
        __syncthreads();

        // pass 1: scores (split-D dot + partner shuffle) + chunk max
        float cmax = -1e30f;
        const int cb = hf * 32;
        for (int j = 0; j < 64; j++) {
            int jg = c0 + j;
            float s0 = 0.f, s1 = 0.f, s2 = 0.f, s3 = 0.f;
#pragma unroll
            for (int c = 0; c < 32; c += 4) {
                s0 = fmaf(q[c + 0], Ks[j][cb + c + 0], s0);
                s1 = fmaf(q[c + 1], Ks[j][cb + c + 1], s1);
                s2 = fmaf(q[c + 2], Ks[j][cb + c + 2], s2);
                s3 = fmaf(q[c + 3], Ks[j][cb + c + 3], s3);
            }
            float part = (s0 + s1) + (s2 + s3);
            part += __shfl_xor_sync(0xffffffffu, part, 1);
            float s = (jg <= i && (i - jg) <= w) ? part * 0.125f : -1e30f;
            if (hf == 0) Ss[qi][(j + qi) & 63] = s;
            cmax = fmaxf(cmax, s);
        }
        __syncwarp();

        // rescale running state
        float m_new = fmaxf(m, cmax);
        float resc = __expf(m - m_new);
        l *= resc;
#pragma unroll
        for (int c = 0; c < 32; c++) acc[c] *= resc;

        // pass 2: exp + PV accumulate (half of V dims per thread)
        for (int j = 0; j < 64; j++) {
            float p = __expf(Ss[qi][(j + qi) & 63] - m_new);
            l += p;
#pragma unroll
            for (int c = 0; c < 32; c++)
                acc[c] = fmaf(p, Vs[j][cb + c], acc[c]);
        }
        m = m_new;
        __syncthreads();
    }

    float inv = 1.f / l;
    float* yr = g_Y + qrow;
#pragma unroll
    for (int c4 = 0; c4 < 32; c4 += 4) {
        float4 o;
        o.x = acc[c4 + 0] * inv; o.y = acc[c4 + 1] * inv;
        o.z = acc[c4 + 2] * inv; o.w = acc[c4 + 3] * inv;
        *(float4*)&yr[c4] = o;
    }
}

// ---------------------------------------------------------------------------
extern "C" void kernel_launch(void* const* d_in, const int* in_sizes, int n_in,
                              void* d_out, int out_size)
{
    const float* x    = (const float*)d_in[0];
    const float* ve   = (const float*)d_in[1];
    const float* cosb = (const float*)d_in[2];
    const float* sinb = (const float*)d_in[3];
    const float* Wq   = (const float*)d_in[4];
    const float* Wk   = (const float*)d_in[5];
    const float* Wv   = (const float*)d_in[6];
    const float* Wo   = (const float*)d_in[7];
    const float* Wg   = (const float*)d_in[8];
    const int*   win  = (const int*)d_in[9];

    float* out = (float*)d_out;

    float* Qp; cudaGetSymbolAddress((void**)&Qp, g_Q);
    float* Kp; cudaGetSymbolAddress((void**)&Kp, g_K);
    float* Vp; cudaGetSymbolAddress((void**)&Vp, g_V);
    float* Yp; cudaGetSymbolAddress((void**)&Yp, g_Y);

    // QKV projections (tf32 mma.sync)
    gemm_tc<<<dim3(QDIM / 128, ROWS / 128), 256>>>(x, Wq, Qp, ROWS, QDIM, Cc);
    gemm_tc<<<dim3(KVDIM / 128, ROWS / 128), 256>>>(x, Wk, Kp, ROWS, KVDIM, Cc);
    gemm_tc<<<dim3(KVDIM / 128, ROWS / 128), 256>>>(x, Wv, Vp, ROWS, KVDIM, Cc);

    // gate + RoPE + RMS-norm
    postproc<<<ROWS, 256>>>(x, ve, cosb, sinb, Wg);

    // windowed attention
    attn<<<dim3(Tt / 64, Hh, Bb), 128>>>(win);

    // output projection
    gemm_tc<<<dim3(QDIM / 128, ROWS / 128), 256>>>(Yp, Wo, out, ROWS, QDIM, Cc);
}

// round 4
// speedup vs baseline: 3.7374x; 2.1825x over previous
#include <cuda_runtime.h>
#include <cuda_bf16.h>
#include <math.h>
#include <cstdint>

// Problem constants
#define Bb 4
#define Tt 1024
#define Cc 1024
#define Hh 16
#define HKV 4
#define Dd 64
#define ROWS (Bb*Tt)          // 4096 tokens
#define QDIM (Hh*Dd)          // 1024
#define KVDIM (HKV*Dd)        // 256
#define GATE_CH 12

// Scratch (no cudaMalloc allowed)
__device__ float g_Q[ROWS * QDIM];    // 16 MB
__device__ float g_K[ROWS * KVDIM];   // 4 MB
__device__ float g_V[ROWS * KVDIM];   // 4 MB
__device__ float g_Y[ROWS * QDIM];    // 16 MB

__device__ __forceinline__ float tf32r(float x) {
    float y;
    asm("cvt.rna.tf32.f32 %0, %1;" : "=f"(y) : "f"(x));
    return y;
}

__device__ __forceinline__ void mma_tf32(float* d,
                                         const uint32_t* a, const uint32_t* b) {
    asm volatile(
        "mma.sync.aligned.m16n8k8.row.col.f32.tf32.tf32.f32 "
        "{%0,%1,%2,%3}, {%4,%5,%6,%7}, {%8,%9}, {%0,%1,%2,%3};"
        : "+f"(d[0]), "+f"(d[1]), "+f"(d[2]), "+f"(d[3])
        : "r"(a[0]), "r"(a[1]), "r"(a[2]), "r"(a[3]),
          "r"(b[0]), "r"(b[1]));
}

// ---------------------------------------------------------------------------
// tf32 mma.sync GEMM core:  C[.,n0..n0+127] = A[M,K] * B[128,K]^T
// BM=BN=128, BK=32, 256 threads (8 warps, 4x2), warp tile 32x64.
// ---------------------------------------------------------------------------
#define BK 32
#define LDS_S (BK + 4)

__device__ __forceinline__ void gemm_body(
    const float* __restrict__ Ab, const float* __restrict__ Bp,
    float* __restrict__ Crow0, int N, int K)
{
    __shared__ uint32_t As[128][LDS_S];
    __shared__ uint32_t Bs[128][LDS_S];

    const int tid = threadIdx.x;
    const int wid = tid >> 5;
    const int lane = tid & 31;
    const int warp_m = wid & 3;
    const int warp_n = wid >> 2;
    const int group = lane >> 2;
    const int kq = lane & 3;

    float acc[2][8][4];
#pragma unroll
    for (int mt = 0; mt < 2; mt++)
#pragma unroll
        for (int nt = 0; nt < 8; nt++)
#pragma unroll
            for (int c = 0; c < 4; c++) acc[mt][nt][c] = 0.f;

    const int nk = K >> 5;

    float4 ra[4], rb[4];
#pragma unroll
    for (int t = 0; t < 4; t++) {
        int idx = tid + t * 256;
        int row = idx >> 3;
        int c4  = (idx & 7) << 2;
        ra[t] = *(const float4*)(Ab + (size_t)row * K + c4);
        rb[t] = *(const float4*)(Bp + (size_t)row * K + c4);
    }

    for (int kc = 0; kc < nk; kc++) {
        if (kc > 0) __syncthreads();
#pragma unroll
        for (int t = 0; t < 4; t++) {
            int idx = tid + t * 256;
            int row = idx >> 3;
            int c4  = (idx & 7) << 2;
            As[row][c4 + 0] = __float_as_uint(tf32r(ra[t].x));
            As[row][c4 + 1] = __float_as_uint(tf32r(ra[t].y));
            As[row][c4 + 2] = __float_as_uint(tf32r(ra[t].z));
            As[row][c4 + 3] = __float_as_uint(tf32r(ra[t].w));
            Bs[row][c4 + 0] = __float_as_uint(tf32r(rb[t].x));
            Bs[row][c4 + 1] = __float_as_uint(tf32r(rb[t].y));
            Bs[row][c4 + 2] = __float_as_uint(tf32r(rb[t].z));
            Bs[row][c4 + 3] = __float_as_uint(tf32r(rb[t].w));
        }
        __syncthreads();

        if (kc + 1 < nk) {
#pragma unroll
            for (int t = 0; t < 4; t++) {
                int idx = tid + t * 256;
                int row = idx >> 3;
                int c4  = (idx & 7) << 2;
                size_t off = (size_t)row * K + (kc + 1) * BK + c4;
                ra[t] = *(const float4*)(Ab + off);
                rb[t] = *(const float4*)(Bp + off);
            }
        }

#pragma unroll
        for (int ks = 0; ks < 4; ks++) {
            const int k0 = ks * 8;
            uint32_t af[2][4];
#pragma unroll
            for (int mt = 0; mt < 2; mt++) {
                int r = warp_m * 32 + mt * 16 + group;
                af[mt][0] = As[r][k0 + kq];
                af[mt][1] = As[r + 8][k0 + kq];
                af[mt][2] = As[r][k0 + kq + 4];
                af[mt][3] = As[r + 8][k0 + kq + 4];
            }
            uint32_t bf[8][2];
#pragma unroll
            for (int nt = 0; nt < 8; nt++) {
                int cn = warp_n * 64 + nt * 8 + group;
                bf[nt][0] = Bs[cn][k0 + kq];
                bf[nt][1] = Bs[cn][k0 + kq + 4];
            }
#pragma unroll
            for (int mt = 0; mt < 2; mt++)
#pragma unroll
                for (int nt = 0; nt < 8; nt++)
                    mma_tf32(acc[mt][nt], af[mt], bf[nt]);
        }
    }

#pragma unroll
    for (int mt = 0; mt < 2; mt++) {
        int r = warp_m * 32 + mt * 16 + group;
#pragma unroll
        for (int nt = 0; nt < 8; nt++) {
            int cn = warp_n * 64 + nt * 8 + 2 * kq;
            *(float2*)(Crow0 + (size_t)r * N + cn) =
                make_float2(acc[mt][nt][0], acc[mt][nt][1]);
            *(float2*)(Crow0 + (size_t)(r + 8) * N + cn) =
                make_float2(acc[mt][nt][2], acc[mt][nt][3]);
        }
    }
}

// Merged QKV projection: grid.x 0..7 -> Q, 8..9 -> K, 10..11 -> V
__global__ __launch_bounds__(256, 1) void gemm_qkv(
    const float* __restrict__ A,
    const float* __restrict__ Wq, const float* __restrict__ Wk,
    const float* __restrict__ Wv,
    float* __restrict__ Qo, float* __restrict__ Ko, float* __restrict__ Vo)
{
    const int bx = blockIdx.x;
    const float* Bp;
    float* Cp;
    int N, nb;
    if (bx < 8)       { Bp = Wq; Cp = Qo; N = QDIM;  nb = bx; }
    else if (bx < 10) { Bp = Wk; Cp = Ko; N = KVDIM; nb = bx - 8; }
    else              { Bp = Wv; Cp = Vo; N = KVDIM; nb = bx - 10; }
    gemm_body(A + (size_t)blockIdx.y * 128 * Cc,
              Bp + (size_t)nb * 128 * Cc,
              Cp + (size_t)blockIdx.y * 128 * N + nb * 128, N, Cc);
}

__global__ __launch_bounds__(256, 1) void gemm_tc(
    const float* __restrict__ A, const float* __restrict__ B,
    float* __restrict__ C, int M, int N, int K)
{
    gemm_body(A + (size_t)blockIdx.y * 128 * K,
              B + (size_t)blockIdx.x * 128 * K,
              C + (size_t)blockIdx.y * 128 * N + blockIdx.x * 128, N, K);
}

// ---------------------------------------------------------------------------
// Postproc: per-token gate+V update, RoPE + RMS-norm on Q and K.
// ---------------------------------------------------------------------------
__global__ __launch_bounds__(256) void postproc(
    const float* __restrict__ x, const float* __restrict__ ve,
    const float* __restrict__ cosb, const float* __restrict__ sinb,
    const float* __restrict__ Wg)
{
    const int row = blockIdx.x;
    const int t = row & (Tt - 1);
    const int warp = threadIdx.x >> 5;
    const int lane = threadIdx.x & 31;

    if (warp < HKV) {
        float p = 0.f;
        if (lane < GATE_CH)
            p = x[(size_t)row * Cc + lane] * Wg[warp * GATE_CH + lane];
#pragma unroll
        for (int o = 16; o > 0; o >>= 1)
            p += __shfl_xor_sync(0xffffffffu, p, o);
        float gate = 3.f / (1.f + __expf(-p));
        size_t base = (size_t)row * KVDIM + warp * Dd;
        g_V[base + lane]      += gate * ve[base + lane];
        g_V[base + 32 + lane] += gate * ve[base + 32 + lane];
    }

    const float cv = cosb[t * 32 + lane];
    const float sv = sinb[t * 32 + lane];
    for (int tsk = warp; tsk < Hh + HKV; tsk += 8) {
        float* ptr = (tsk < Hh)
            ? (g_Q + (size_t)row * QDIM + tsk * Dd)
            : (g_K + (size_t)row * KVDIM + (tsk - Hh) * Dd);
        float x1 = ptr[lane];
        float x2 = ptr[lane + 32];
        float y1 = x1 * cv + x2 * sv;
        float y2 = x2 * cv - x1 * sv;
        float ss = y1 * y1 + y2 * y2;
#pragma unroll
        for (int o = 16; o > 0; o >>= 1)
            ss += __shfl_xor_sync(0xffffffffu, ss, o);
        float sc = 1.2f * rsqrtf(ss * (1.0f / Dd) + 1.1920929e-7f);
        ptr[lane]      = y1 * sc;
        ptr[lane + 32] = y2 * sc;
    }
}

// ---------------------------------------------------------------------------
// mma.sync flash attention. CTA = (qtile64, kv-head g, batch b), covering all
// 4 GQA q-heads: M=256 score rows (4 heads x 64 queries), keys in 64-chunks.
// 8 warps; warp w owns rows w*32..w*32+31 (one head per warp pair).
// ---------------------------------------------------------------------------
#define SST 68   // smem row stride (floats)

__global__ __launch_bounds__(256, 1) void attn_mma(const int* __restrict__ wptr)
{
    extern __shared__ float dsm[];
    float* Ss = dsm;                        // [256][SST] P-staging (warp-private rows)
    float* Ks = dsm + 256 * SST;            // [64][SST]
    float* Vs = Ks + 64 * SST;              // [64][SST]

    const int qt = blockIdx.x, g = blockIdx.y, b = blockIdx.z;
    const int tid = threadIdx.x;
    const int wid = tid >> 5;
    const int lane = tid & 31;
    const int group = lane >> 2;
    const int kq = lane & 3;
    const int rbase = wid * 32;
    const int head = g * 4 + (wid >> 1);
    const int q0 = qt * 64;
    const int qloc0 = (wid & 1) * 32;       // local query offset of this warp

    // Q fragments (held in registers for whole CTA lifetime), tf32-rounded
    uint32_t qf[2][8][4];
    {
        const float* Qb = g_Q + ((size_t)(b * Tt + q0)) * QDIM + head * Dd;
#pragma unroll
        for (int mt = 0; mt < 2; mt++) {
            int r0 = qloc0 + mt * 16 + group;
#pragma unroll
            for (int ks = 0; ks < 8; ks++) {
                int k0 = ks * 8 + kq;
                qf[mt][ks][0] = __float_as_uint(tf32r(Qb[(size_t)r0 * QDIM + k0]));
                qf[mt][ks][1] = __float_as_uint(tf32r(Qb[(size_t)(r0 + 8) * QDIM + k0]));
                qf[mt][ks][2] = __float_as_uint(tf32r(Qb[(size_t)r0 * QDIM + k0 + 4]));
                qf[mt][ks][3] = __float_as_uint(tf32r(Qb[(size_t)(r0 + 8) * QDIM + k0 + 4]));
            }
        }
    }

    float oacc[2][8][4];
#pragma unroll
    for (int mt = 0; mt < 2; mt++)
#pragma unroll
        for (int nt = 0; nt < 8; nt++)
#pragma unroll
            for (int c = 0; c < 4; c++) oacc[mt][nt][c] = 0.f;

    float mrow[2][2] = {{-1e30f, -1e30f}, {-1e30f, -1e30f}};
    float lrow[2][2] = {{0.f, 0.f}, {0.f, 0.f}};

    const int w = wptr[0];
    int jmin = q0 - w; if (jmin < 0) jmin = 0;

    for (int c0 = (jmin >> 6) << 6; c0 <= q0; c0 += 64) {
        // load K,V chunk (tf32-rounded at store)
#pragma unroll
        for (int t = 0; t < 4; t++) {
            int idx = tid + t * 256;            // 0..1023
            int key = idx >> 4;
            int d4  = (idx & 15) << 2;
            size_t src = ((size_t)(b * Tt + c0 + key)) * KVDIM + g * Dd + d4;
            float4 kv = *(const float4*)&g_K[src];
            float4 vv = *(const float4*)&g_V[src];
            float* kd = &Ks[key * SST + d4];
            kd[0] = tf32r(kv.x); kd[1] = tf32r(kv.y);
            kd[2] = tf32r(kv.z); kd[3] = tf32r(kv.w);
            float* vd = &Vs[key * SST + d4];
            vd[0] = tf32r(vv.x); vd[1] = tf32r(vv.y);
            vd[2] = tf32r(vv.z); vd[3] = tf32r(vv.w);
        }
        __syncthreads();

        // scores: S = Q * K^T  (acc registers)
        float sacc[2][8][4];
#pragma unroll
        for (int mt = 0; mt < 2; mt++)
#pragma unroll
            for (int nt = 0; nt < 8; nt++)
#pragma unroll
                for (int c = 0; c < 4; c++) sacc[mt][nt][c] = 0.f;

#pragma unroll
        for (int ks = 0; ks < 8; ks++) {
            const int k0 = ks * 8;
            uint32_t bf[8][2];
#pragma unroll
            for (int nt = 0; nt < 8; nt++) {
                bf[nt][0] = __float_as_uint(Ks[(nt * 8 + group) * SST + k0 + kq]);
                bf[nt][1] = __float_as_uint(Ks[(nt * 8 + group) * SST + k0 + kq + 4]);
            }
#pragma unroll
            for (int mt = 0; mt < 2; mt++)
#pragma unroll
                for (int nt = 0; nt < 8; nt++)
                    mma_tf32(sacc[mt][nt], qf[mt][ks], bf[nt]);
        }

        // mask + scale + online softmax per warp-owned rows
#pragma unroll
        for (int mt = 0; mt < 2; mt++) {
            const int i0 = q0 + qloc0 + mt * 16 + group;   // row of c0,c1
            const int i1 = i0 + 8;                          // row of c2,c3
            float cmax0 = -1e30f, cmax1 = -1e30f;
#pragma unroll
            for (int nt = 0; nt < 8; nt++) {
                int jg = c0 + nt * 8 + 2 * kq;
                float s;
                s = (jg     <= i0 && (i0 - jg)     <= w) ? sacc[mt][nt][0] * 0.125f : -1e30f;
                sacc[mt][nt][0] = s; cmax0 = fmaxf(cmax0, s);
                s = (jg + 1 <= i0 && (i0 - jg - 1) <= w) ? sacc[mt][nt][1] * 0.125f : -1e30f;
                sacc[mt][nt][1] = s; cmax0 = fmaxf(cmax0, s);
                s = (jg     <= i1 && (i1 - jg)     <= w) ? sacc[mt][nt][2] * 0.125f : -1e30f;
                sacc[mt][nt][2] = s; cmax1 = fmaxf(cmax1, s);
                s = (jg + 1 <= i1 && (i1 - jg - 1) <= w) ? sacc[mt][nt][3] * 0.125f : -1e30f;
                sacc[mt][nt][3] = s; cmax1 = fmaxf(cmax1, s);
            }
            // quad reduction over kq lanes
            cmax0 = fmaxf(cmax0, __shfl_xor_sync(0xffffffffu, cmax0, 1));
            cmax0 = fmaxf(cmax0, __shfl_xor_sync(0xffffffffu, cmax0, 2));
            cmax1 = fmaxf(cmax1, __shfl_xor_sync(0xffffffffu, cmax1, 1));
            cmax1 = fmaxf(cmax1, __shfl_xor_sync(0xffffffffu, cmax1, 2));

            float mn0 = fmaxf(mrow[mt][0], cmax0);
            float mn1 = fmaxf(mrow[mt][1], cmax1);
            float r0 = __expf(mrow[mt][0] - mn0);
            float r1 = __expf(mrow[mt][1] - mn1);
            mrow[mt][0] = mn0; mrow[mt][1] = mn1;
            lrow[mt][0] *= r0; lrow[mt][1] *= r1;
#pragma unroll
            for (int nt = 0; nt < 8; nt++) {
                oacc[mt][nt][0] *= r0; oacc[mt][nt][1] *= r0;
                oacc[mt][nt][2] *= r1; oacc[mt][nt][3] *= r1;
            }
            // exp, tf32-round, accumulate l, stage P
            const int prow0 = rbase + mt * 16 + group;
#pragma unroll
            for (int nt = 0; nt < 8; nt++) {
                float p0 = tf32r(__expf(sacc[mt][nt][0] - mn0));
                float p1 = tf32r(__expf(sacc[mt][nt][1] - mn0));
                float p2 = tf32r(__expf(sacc[mt][nt][2] - mn1));
                float p3 = tf32r(__expf(sacc[mt][nt][3] - mn1));
                lrow[mt][0] += p0 + p1;
                lrow[mt][1] += p2 + p3;
                *(float2*)&Ss[prow0 * SST + nt * 8 + 2 * kq] = make_float2(p0, p1);
                *(float2*)&Ss[(prow0 + 8) * SST + nt * 8 + 2 * kq] = make_float2(p2, p3);
            }
        }
        __syncwarp();

        // PV: O += P * V
#pragma unroll
        for (int ks = 0; ks < 8; ks++) {
            const int k0 = ks * 8;
            uint32_t vf[8][2];
#pragma unroll
            for (int nt = 0; nt < 8; nt++) {
                vf[nt][0] = __float_as_uint(Vs[(k0 + kq) * SST + nt * 8 + group]);
                vf[nt][1] = __float_as_uint(Vs[(k0 + kq + 4) * SST + nt * 8 + group]);
            }
            uint32_t af[2][4];
#pragma unroll
            for (int mt = 0; mt < 2; mt++) {
                const int pr = rbase + mt * 16 + group;
                af[mt][0] = __float_as_uint(Ss[pr * SST + k0 + kq]);
                af[mt][1] = __float_as_uint(Ss[(pr + 8) * SST + k0 + kq]);
                af[mt][2] = __float_as_uint(Ss[pr * SST + k0 + kq + 4]);
                af[mt][3] = __float_as_uint(Ss[(pr + 8) * SST + k0 + kq + 4]);
            }
#pragma unroll
            for (int mt = 0; mt < 2; mt++)
#pragma unroll
                for (int nt = 0; nt < 8; nt++)
                    mma_tf32(oacc[mt][nt], af[mt], vf[nt]);
        }
        __syncthreads();
    }

    // finalize: reduce l over quad, divide, store
#pragma unroll
    for (int mt = 0; mt < 2; mt++) {
        float l0 = lrow[mt][0], l1 = lrow[mt][1];
        l0 += __shfl_xor_sync(0xffffffffu, l0, 1);
        l0 += __shfl_xor_sync(0xffffffffu, l0, 2);
        l1 += __shfl_xor_sync(0xffffffffu, l1, 1);
        l1 += __shfl_xor_sync(0xffffffffu, l1, 2);
        float inv0 = 1.f / l0, inv1 = 1.f / l1;
        int r0 = q0 + qloc0 + mt * 16 + group;
        float* Y0 = g_Y + ((size_t)(b * Tt + r0)) * QDIM + head * Dd;
        float* Y1 = g_Y + ((size_t)(b * Tt + r0 + 8)) * QDIM + head * Dd;
#pragma unroll
        for (int nt = 0; nt < 8; nt++) {
            int cn = nt * 8 + 2 * kq;
            *(float2*)(Y0 + cn) = make_float2(oacc[mt][nt][0] * inv0,
                                              oacc[mt][nt][1] * inv0);
            *(float2*)(Y1 + cn) = make_float2(oacc[mt][nt][2] * inv1,
                                              oacc[mt][nt][3] * inv1);
        }
    }
}

// ---------------------------------------------------------------------------
extern "C" void kernel_launch(void* const* d_in, const int* in_sizes, int n_in,
                              void* d_out, int out_size)
{
    const float* x    = (const float*)d_in[0];
    const float* ve   = (const float*)d_in[1];
    const float* cosb = (const float*)d_in[2];
    const float* sinb = (const float*)d_in[3];
    const float* Wq   = (const float*)d_in[4];
    const float* Wk   = (const float*)d_in[5];
    const float* Wv   = (const float*)d_in[6];
    const float* Wo   = (const float*)d_in[7];
    const float* Wg   = (const float*)d_in[8];
    const int*   win  = (const int*)d_in[9];

    float* out = (float*)d_out;

    float* Qp; cudaGetSymbolAddress((void**)&Qp, g_Q);
    float* Kp; cudaGetSymbolAddress((void**)&Kp, g_K);
    float* Vp; cudaGetSymbolAddress((void**)&Vp, g_V);
    float* Yp; cudaGetSymbolAddress((void**)&Yp, g_Y);

    static bool attr_set = false;
    if (!attr_set) {
        cudaFuncSetAttribute(attn_mma,
            cudaFuncAttributeMaxDynamicSharedMemorySize, (256 + 128) * SST * 4);
        attr_set = true;
    }

    // merged QKV projections (tf32 mma.sync)
    gemm_qkv<<<dim3(12, ROWS / 128), 256>>>(x, Wq, Wk, Wv, Qp, Kp, Vp);

    // gate + RoPE + RMS-norm
    postproc<<<ROWS, 256>>>(x, ve, cosb, sinb, Wg);

    // mma flash attention
    attn_mma<<<dim3(Tt / 64, HKV, Bb), 256, (256 + 128) * SST * 4>>>(win);

    // output projection
    gemm_tc<<<dim3(QDIM / 128, ROWS / 128), 256>>>(Yp, Wo, out, ROWS, QDIM, Cc);
}

// round 6
// speedup vs baseline: 3.9612x; 1.0599x over previous
#include <cuda_runtime.h>
#include <cuda_bf16.h>
#include <math.h>
#include <cstdint>

// Problem constants
#define Bb 4
#define Tt 1024
#define Cc 1024
#define Hh 16
#define HKV 4
#define Dd 64
#define ROWS (Bb*Tt)          // 4096 tokens
#define QDIM (Hh*Dd)          // 1024
#define KVDIM (HKV*Dd)        // 256
#define GATE_CH 12

// Scratch (no cudaMalloc allowed)
__device__ float g_Q[ROWS * QDIM];    // 16 MB
__device__ float g_K[ROWS * KVDIM];   // 4 MB
__device__ float g_V[ROWS * KVDIM];   // 4 MB
__device__ float g_Y[ROWS * QDIM];    // 16 MB

__device__ __forceinline__ float tf32r(float x) {
    float y;
    asm("cvt.rna.tf32.f32 %0, %1;" : "=f"(y) : "f"(x));
    return y;
}
__device__ __forceinline__ uint32_t ldr(const float* p) {
    return __float_as_uint(tf32r(*p));
}

__device__ __forceinline__ void mma_tf32(float* d,
                                         const uint32_t* a, const uint32_t* b) {
    asm volatile(
        "mma.sync.aligned.m16n8k8.row.col.f32.tf32.tf32.f32 "
        "{%0,%1,%2,%3}, {%4,%5,%6,%7}, {%8,%9}, {%0,%1,%2,%3};"
        : "+f"(d[0]), "+f"(d[1]), "+f"(d[2]), "+f"(d[3])
        : "r"(a[0]), "r"(a[1]), "r"(a[2]), "r"(a[3]),
          "r"(b[0]), "r"(b[1]));
}

__device__ __forceinline__ void cpa16(float* s, const float* g) {
    uint32_t sa = (uint32_t)__cvta_generic_to_shared(s);
    asm volatile("cp.async.cg.shared.global [%0], [%1], 16;"
                 :: "r"(sa), "l"(g) : "memory");
}

// ---------------------------------------------------------------------------
// tf32 mma.sync GEMM core:  C_tile = A[128,K] * B[128,K]^T
// BK=32, 256 threads (8 warps, 4x2), warp tile 32x64.
// cp.async double-buffered smem; tf32 rounding at fragment load.
// ---------------------------------------------------------------------------
#define LDS_S 36                  // 32 + 4 pad (words)
#define STG (128 * LDS_S)         // floats per stage per operand

__device__ __forceinline__ void gemm_body(
    const float* __restrict__ Ab, const float* __restrict__ Bp,
    float* __restrict__ Crow0, int N, int K, float* __restrict__ sm)
{
    float* smA = sm;              // 2 stages
    float* smB = sm + 2 * STG;

    const int tid = threadIdx.x;
    const int wid = tid >> 5;
    const int lane = tid & 31;
    const int warp_m = wid & 3;
    const int warp_n = wid >> 2;
    const int group = lane >> 2;
    const int kq = lane & 3;

    float acc[2][8][4];
#pragma unroll
    for (int mt = 0; mt < 2; mt++)
#pragma unroll
        for (int nt = 0; nt < 8; nt++)
#pragma unroll
            for (int c = 0; c < 4; c++) acc[mt][nt][c] = 0.f;

    const int nk = K >> 5;

    // prologue: async-copy chunk 0 into stage 0
#pragma unroll
    for (int t = 0; t < 4; t++) {
        int idx = tid + t * 256;          // 0..1023
        int row = idx >> 3;
        int c4  = (idx & 7) << 2;
        cpa16(smA + row * LDS_S + c4, Ab + (size_t)row * K + c4);
        cpa16(smB + row * LDS_S + c4, Bp + (size_t)row * K + c4);
    }
    asm volatile("cp.async.commit_group;" ::: "memory");

    for (int kc = 0; kc < nk; kc++) {
        asm volatile("cp.async.wait_group 0;" ::: "memory");
        __syncthreads();   // data visible + everyone done with the other stage

        if (kc + 1 < nk) {
            float* dA = smA + ((kc + 1) & 1) * STG;
            float* dB = smB + ((kc + 1) & 1) * STG;
            const int koff = (kc + 1) << 5;
#pragma unroll
            for (int t = 0; t < 4; t++) {
                int idx = tid + t * 256;
                int row = idx >> 3;
                int c4  = (idx & 7) << 2;
                cpa16(dA + row * LDS_S + c4, Ab + (size_t)row * K + koff + c4);
                cpa16(dB + row * LDS_S + c4, Bp + (size_t)row * K + koff + c4);
            }
            asm volatile("cp.async.commit_group;" ::: "memory");
        }

        const float* As = smA + (kc & 1) * STG;
        const float* Bs = smB + (kc & 1) * STG;
#pragma unroll
        for (int ks = 0; ks < 4; ks++) {
            const int k0 = ks * 8;
            uint32_t af[2][4];
#pragma unroll
            for (int mt = 0; mt < 2; mt++) {
                const float* ar = As + (warp_m * 32 + mt * 16 + group) * LDS_S + k0 + kq;
                af[mt][0] = ldr(ar);
                af[mt][1] = ldr(ar + 8 * LDS_S);
                af[mt][2] = ldr(ar + 4);
                af[mt][3] = ldr(ar + 8 * LDS_S + 4);
            }
            uint32_t bf[8][2];
#pragma unroll
            for (int nt = 0; nt < 8; nt++) {
                const float* br = Bs + (warp_n * 64 + nt * 8 + group) * LDS_S + k0 + kq;
                bf[nt][0] = ldr(br);
                bf[nt][1] = ldr(br + 4);
            }
#pragma unroll
            for (int mt = 0; mt < 2; mt++)
#pragma unroll
                for (int nt = 0; nt < 8; nt++)
                    mma_tf32(acc[mt][nt], af[mt], bf[nt]);
        }
    }

#pragma unroll
    for (int mt = 0; mt < 2; mt++) {
        int r = warp_m * 32 + mt * 16 + group;
#pragma unroll
        for (int nt = 0; nt < 8; nt++) {
            int cn = warp_n * 64 + nt * 8 + 2 * kq;
            *(float2*)(Crow0 + (size_t)r * N + cn) =
                make_float2(acc[mt][nt][0], acc[mt][nt][1]);
            *(float2*)(Crow0 + (size_t)(r + 8) * N + cn) =
                make_float2(acc[mt][nt][2], acc[mt][nt][3]);
        }
    }
}

// Merged QKV projection: grid.x 0..7 -> Q, 8..9 -> K, 10..11 -> V
__global__ __launch_bounds__(256, 2) void gemm_qkv(
    const float* __restrict__ A,
    const float* __restrict__ Wq, const float* __restrict__ Wk,
    const float* __restrict__ Wv,
    float* __restrict__ Qo, float* __restrict__ Ko, float* __restrict__ Vo)
{
    extern __shared__ float sm[];
    const int bx = blockIdx.x;
    const float* Bp;
    float* Cp;
    int N, nb;
    if (bx < 8)       { Bp = Wq; Cp = Qo; N = QDIM;  nb = bx; }
    else if (bx < 10) { Bp = Wk; Cp = Ko; N = KVDIM; nb = bx - 8; }
    else              { Bp = Wv; Cp = Vo; N = KVDIM; nb = bx - 10; }
    gemm_body(A + (size_t)blockIdx.y * 128 * Cc,
              Bp + (size_t)nb * 128 * Cc,
              Cp + (size_t)blockIdx.y * 128 * N + nb * 128, N, Cc, sm);
}

__global__ __launch_bounds__(256, 2) void gemm_tc(
    const float* __restrict__ A, const float* __restrict__ B,
    float* __restrict__ C, int M, int N, int K)
{
    extern __shared__ float sm[];
    gemm_body(A + (size_t)blockIdx.y * 128 * K,
              B + (size_t)blockIdx.x * 128 * K,
              C + (size_t)blockIdx.y * 128 * N + blockIdx.x * 128, N, K, sm);
}

// ---------------------------------------------------------------------------
// Postproc: per-token gate+V update, RoPE + RMS-norm on Q and K.
// ---------------------------------------------------------------------------
__global__ __launch_bounds__(256) void postproc(
    const float* __restrict__ x, const float* __restrict__ ve,
    const float* __restrict__ cosb, const float* __restrict__ sinb,
    const float* __restrict__ Wg)
{
    const int row = blockIdx.x;
    const int t = row & (Tt - 1);
    const int warp = threadIdx.x >> 5;
    const int lane = threadIdx.x & 31;

    if (warp < HKV) {
        float p = 0.f;
        if (lane < GATE_CH)
            p = x[(size_t)row * Cc + lane] * Wg[warp * GATE_CH + lane];
#pragma unroll
        for (int o = 16; o > 0; o >>= 1)
            p += __shfl_xor_sync(0xffffffffu, p, o);
        float gate = 3.f / (1.f + __expf(-p));
        size_t base = (size_t)row * KVDIM + warp * Dd;
        g_V[base + lane]      += gate * ve[base + lane];
        g_V[base + 32 + lane] += gate * ve[base + 32 + lane];
    }

    const float cv = cosb[t * 32 + lane];
    const float sv = sinb[t * 32 + lane];
    for (int tsk = warp; tsk < Hh + HKV; tsk += 8) {
        float* ptr = (tsk < Hh)
            ? (g_Q + (size_t)row * QDIM + tsk * Dd)
            : (g_K + (size_t)row * KVDIM + (tsk - Hh) * Dd);
        float x1 = ptr[lane];
        float x2 = ptr[lane + 32];
        float y1 = x1 * cv + x2 * sv;
        float y2 = x2 * cv - x1 * sv;
        float ss = y1 * y1 + y2 * y2;
#pragma unroll
        for (int o = 16; o > 0; o >>= 1)
            ss += __shfl_xor_sync(0xffffffffu, ss, o);
        float sc = 1.2f * rsqrtf(ss * (1.0f / Dd) + 1.1920929e-7f);
        ptr[lane]      = y1 * sc;
        ptr[lane + 32] = y2 * sc;
    }
}

// ---------------------------------------------------------------------------
// mma.sync flash attention. CTA = (qtile64, kv-head g, batch b), covering all
// 4 GQA q-heads: M=256 score rows (4 heads x 64 queries), keys in 64-chunks.
// 8 warps; warp w owns rows w*32..w*32+31.
// ---------------------------------------------------------------------------
#define SST 68   // smem row stride (floats)

__global__ __launch_bounds__(256, 1) void attn_mma(const int* __restrict__ wptr)
{
    extern __shared__ float dsm[];
    float* Ss = dsm;                        // [256][SST] P-staging (warp-private rows)
    float* Ks = dsm + 256 * SST;            // [64][SST]
    float* Vs = Ks + 64 * SST;              // [64][SST]

    const int qt = blockIdx.x, g = blockIdx.y, b = blockIdx.z;
    const int tid = threadIdx.x;
    const int wid = tid >> 5;
    const int lane = tid & 31;
    const int group = lane >> 2;
    const int kq = lane & 3;
    const int rbase = wid * 32;
    const int head = g * 4 + (wid >> 1);
    const int q0 = qt * 64;
    const int qloc0 = (wid & 1) * 32;

    // Q fragments (registers for CTA lifetime), tf32-rounded
    uint32_t qf[2][8][4];
    {
        const float* Qb = g_Q + ((size_t)(b * Tt + q0)) * QDIM + head * Dd;
#pragma unroll
        for (int mt = 0; mt < 2; mt++) {
            int r0 = qloc0 + mt * 16 + group;
#pragma unroll
            for (int ks = 0; ks < 8; ks++) {
                int k0 = ks * 8 + kq;
                qf[mt][ks][0] = __float_as_uint(tf32r(Qb[(size_t)r0 * QDIM + k0]));
                qf[mt][ks][1] = __float_as_uint(tf32r(Qb[(size_t)(r0 + 8) * QDIM + k0]));
                qf[mt][ks][2] = __float_as_uint(tf32r(Qb[(size_t)r0 * QDIM + k0 + 4]));
                qf[mt][ks][3] = __float_as_uint(tf32r(Qb[(size_t)(r0 + 8) * QDIM + k0 + 4]));
            }
        }
    }

    float oacc[2][8][4];
#pragma unroll
    for (int mt = 0; mt < 2; mt++)
#pragma unroll
        for (int nt = 0; nt < 8; nt++)
#pragma unroll
            for (int c = 0; c < 4; c++) oacc[mt][nt][c] = 0.f;

    float mrow[2][2] = {{-1e30f, -1e30f}, {-1e30f, -1e30f}};
    float lrow[2][2] = {{0.f, 0.f}, {0.f, 0.f}};

    const int w = wptr[0];
    int jmin = q0 - w; if (jmin < 0) jmin = 0;

    for (int c0 = (jmin >> 6) << 6; c0 <= q0; c0 += 64) {
#pragma unroll
        for (int t = 0; t < 4; t++) {
            int idx = tid + t * 256;
            int key = idx >> 4;
            int d4  = (idx & 15) << 2;
            size_t src = ((size_t)(b * Tt + c0 + key)) * KVDIM + g * Dd + d4;
            float4 kv = *(const float4*)&g_K[src];
            float4 vv = *(const float4*)&g_V[src];
            float* kd = &Ks[key * SST + d4];
            kd[0] = tf32r(kv.x); kd[1] = tf32r(kv.y);
            kd[2] = tf32r(kv.z); kd[3] = tf32r(kv.w);
            float* vd = &Vs[key * SST + d4];
            vd[0] = tf32r(vv.x); vd[1] = tf32r(vv.y);
            vd[2] = tf32r(vv.z); vd[3] = tf32r(vv.w);
        }
        __syncthreads();

        float sacc[2][8][4];
#pragma unroll
        for (int mt = 0; mt < 2; mt++)
#pragma unroll
            for (int nt = 0; nt < 8; nt++)
#pragma unroll
                for (int c = 0; c < 4; c++) sacc[mt][nt][c] = 0.f;

#pragma unroll
        for (int ks = 0; ks < 8; ks++) {
            const int k0 = ks * 8;
            uint32_t bf[8][2];
#pragma unroll
            for (int nt = 0; nt < 8; nt++) {
                bf[nt][0] = __float_as_uint(Ks[(nt * 8 + group) * SST + k0 + kq]);
                bf[nt][1] = __float_as_uint(Ks[(nt * 8 + group) * SST + k0 + kq + 4]);
            }
#pragma unroll
            for (int mt = 0; mt < 2; mt++)
#pragma unroll
                for (int nt = 0; nt < 8; nt++)
                    mma_tf32(sacc[mt][nt], qf[mt][ks], bf[nt]);
        }

#pragma unroll
        for (int mt = 0; mt < 2; mt++) {
            const int i0 = q0 + qloc0 + mt * 16 + group;
            const int i1 = i0 + 8;
            float cmax0 = -1e30f, cmax1 = -1e30f;
#pragma unroll
            for (int nt = 0; nt < 8; nt++) {
                int jg = c0 + nt * 8 + 2 * kq;
                float s;
                s = (jg     <= i0 && (i0 - jg)     <= w) ? sacc[mt][nt][0] * 0.125f : -1e30f;
                sacc[mt][nt][0] = s; cmax0 = fmaxf(cmax0, s);
                s = (jg + 1 <= i0 && (i0 - jg - 1) <= w) ? sacc[mt][nt][1] * 0.125f : -1e30f;
                sacc[mt][nt][1] = s; cmax0 = fmaxf(cmax0, s);
                s = (jg     <= i1 && (i1 - jg)     <= w) ? sacc[mt][nt][2] * 0.125f : -1e30f;
                sacc[mt][nt][2] = s; cmax1 = fmaxf(cmax1, s);
                s = (jg + 1 <= i1 && (i1 - jg - 1) <= w) ? sacc[mt][nt][3] * 0.125f : -1e30f;
                sacc[mt][nt][3] = s; cmax1 = fmaxf(cmax1, s);
            }
            cmax0 = fmaxf(cmax0, __shfl_xor_sync(0xffffffffu, cmax0, 1));
            cmax0 = fmaxf(cmax0, __shfl_xor_sync(0xffffffffu, cmax0, 2));
            cmax1 = fmaxf(cmax1, __shfl_xor_sync(0xffffffffu, cmax1, 1));
            cmax1 = fmaxf(cmax1, __shfl_xor_sync(0xffffffffu, cmax1, 2));

            float mn0 = fmaxf(mrow[mt][0], cmax0);
            float mn1 = fmaxf(mrow[mt][1], cmax1);
            float r0 = __expf(mrow[mt][0] - mn0);
            float r1 = __expf(mrow[mt][1] - mn1);
            mrow[mt][0] = mn0; mrow[mt][1] = mn1;
            lrow[mt][0] *= r0; lrow[mt][1] *= r1;
#pragma unroll
            for (int nt = 0; nt < 8; nt++) {
                oacc[mt][nt][0] *= r0; oacc[mt][nt][1] *= r0;
                oacc[mt][nt][2] *= r1; oacc[mt][nt][3] *= r1;
            }
            const int prow0 = rbase + mt * 16 + group;
#pragma unroll
            for (int nt = 0; nt < 8; nt++) {
                float p0 = tf32r(__expf(sacc[mt][nt][0] - mn0));
                float p1 = tf32r(__expf(sacc[mt][nt][1] - mn0));
                float p2 = tf32r(__expf(sacc[mt][nt][2] - mn1));
                float p3 = tf32r(__expf(sacc[mt][nt][3] - mn1));
                lrow[mt][0] += p0 + p1;
                lrow[mt][1] += p2 + p3;
                *(float2*)&Ss[prow0 * SST + nt * 8 + 2 * kq] = make_float2(p0, p1);
                *(float2*)&Ss[(prow0 + 8) * SST + nt * 8 + 2 * kq] = make_float2(p2, p3);
            }
        }
        __syncwarp();

#pragma unroll
        for (int ks = 0; ks < 8; ks++) {
            const int k0 = ks * 8;
            uint32_t vf[8][2];
#pragma unroll
            for (int nt = 0; nt < 8; nt++) {
                vf[nt][0] = __float_as_uint(Vs[(k0 + kq) * SST + nt * 8 + group]);
                vf[nt][1] = __float_as_uint(Vs[(k0 + kq + 4) * SST + nt * 8 + group]);
            }
            uint32_t af[2][4];
#pragma unroll
            for (int mt = 0; mt < 2; mt++) {
                const int pr = rbase + mt * 16 + group;
                af[mt][0] = __float_as_uint(Ss[pr * SST + k0 + kq]);
                af[mt][1] = __float_as_uint(Ss[(pr + 8) * SST + k0 + kq]);
                af[mt][2] = __float_as_uint(Ss[pr * SST + k0 + kq + 4]);
                af[mt][3] = __float_as_uint(Ss[(pr + 8) * SST + k0 + kq + 4]);
            }
#pragma unroll
            for (int mt = 0; mt < 2; mt++)
#pragma unroll
                for (int nt = 0; nt < 8; nt++)
                    mma_tf32(oacc[mt][nt], af[mt], vf[nt]);
        }
        __syncthreads();
    }

#pragma unroll
    for (int mt = 0; mt < 2; mt++) {
        float l0 = lrow[mt][0], l1 = lrow[mt][1];
        l0 += __shfl_xor_sync(0xffffffffu, l0, 1);
        l0 += __shfl_xor_sync(0xffffffffu, l0, 2);
        l1 += __shfl_xor_sync(0xffffffffu, l1, 1);
        l1 += __shfl_xor_sync(0xffffffffu, l1, 2);
        float inv0 = 1.f / l0, inv1 = 1.f / l1;
        int r0 = q0 + qloc0 + mt * 16 + group;
        float* Y0 = g_Y + ((size_t)(b * Tt + r0)) * QDIM + head * Dd;
        float* Y1 = g_Y + ((size_t)(b * Tt + r0 + 8)) * QDIM + head * Dd;
#pragma unroll
        for (int nt = 0; nt < 8; nt++) {
            int cn = nt * 8 + 2 * kq;
            *(float2*)(Y0 + cn) = make_float2(oacc[mt][nt][0] * inv0,
                                              oacc[mt][nt][1] * inv0);
            *(float2*)(Y1 + cn) = make_float2(oacc[mt][nt][2] * inv1,
                                              oacc[mt][nt][3] * inv1);
        }
    }
}

// ---------------------------------------------------------------------------
extern "C" void kernel_launch(void* const* d_in, const int* in_sizes, int n_in,
                              void* d_out, int out_size)
{
    const float* x    = (const float*)d_in[0];
    const float* ve   = (const float*)d_in[1];
    const float* cosb = (const float*)d_in[2];
    const float* sinb = (const float*)d_in[3];
    const float* Wq   = (const float*)d_in[4];
    const float* Wk   = (const float*)d_in[5];
    const float* Wv   = (const float*)d_in[6];
    const float* Wo   = (const float*)d_in[7];
    const float* Wg   = (const float*)d_in[8];
    const int*   win  = (const int*)d_in[9];

    float* out = (float*)d_out;

    float* Qp; cudaGetSymbolAddress((void**)&Qp, g_Q);
    float* Kp; cudaGetSymbolAddress((void**)&Kp, g_K);
    float* Vp; cudaGetSymbolAddress((void**)&Vp, g_V);
    float* Yp; cudaGetSymbolAddress((void**)&Yp, g_Y);

    const int GEMM_SMEM = 4 * STG * 4;   // 73728 bytes
    cudaFuncSetAttribute(gemm_qkv,
        cudaFuncAttributeMaxDynamicSharedMemorySize, GEMM_SMEM);
    cudaFuncSetAttribute(gemm_tc,
        cudaFuncAttributeMaxDynamicSharedMemorySize, GEMM_SMEM);
    cudaFuncSetAttribute(attn_mma,
        cudaFuncAttributeMaxDynamicSharedMemorySize, (256 + 128) * SST * 4);

    // merged QKV projections (tf32 mma.sync)
    gemm_qkv<<<dim3(12, ROWS / 128), 256, GEMM_SMEM>>>(x, Wq, Wk, Wv, Qp, Kp, Vp);

    // gate + RoPE + RMS-norm
    postproc<<<ROWS, 256>>>(x, ve, cosb, sinb, Wg);

    // mma flash attention
    attn_mma<<<dim3(Tt / 64, HKV, Bb), 256, (256 + 128) * SST * 4>>>(win);

    // output projection
    gemm_tc<<<dim3(QDIM / 128, ROWS / 128), 256, GEMM_SMEM>>>(Yp, Wo, out, ROWS, QDIM, Cc);
}

// round 7
// speedup vs baseline: 4.1711x; 1.0530x over previous
#include <cuda_runtime.h>
#include <cuda_bf16.h>
#include <math.h>
#include <cstdint>

// Problem constants
#define Bb 4
#define Tt 1024
#define Cc 1024
#define Hh 16
#define HKV 4
#define Dd 64
#define ROWS (Bb*Tt)          // 4096 tokens
#define QDIM (Hh*Dd)          // 1024
#define KVDIM (HKV*Dd)        // 256
#define GATE_CH 12

#define XN  (ROWS * Cc)       // 4194304
#define WQN (QDIM * Cc)       // 1048576
#define WKN (KVDIM * Cc)      // 262144
#define WON (Cc * Cc)         // 1048576

// Scratch (no cudaMalloc allowed)
__device__ float g_Q[ROWS * QDIM];    // 16 MB
__device__ float g_K[ROWS * KVDIM];   // 4 MB
__device__ float g_V[ROWS * KVDIM];   // 4 MB
__device__ float g_Y[ROWS * QDIM];    // 16 MB
__device__ float g_Xr[XN];            // 16 MB  tf32-rounded x
__device__ float g_Wqr[WQN];          // 4 MB
__device__ float g_Wkr[WKN];          // 1 MB
__device__ float g_Wvr[WKN];          // 1 MB
__device__ float g_Wor[WON];          // 4 MB

__device__ __forceinline__ float tf32r(float x) {
    float y;
    asm("cvt.rna.tf32.f32 %0, %1;" : "=f"(y) : "f"(x));
    return y;
}

__device__ __forceinline__ void mma_tf32(float* d,
                                         const uint32_t* a, const uint32_t* b) {
    asm volatile(
        "mma.sync.aligned.m16n8k8.row.col.f32.tf32.tf32.f32 "
        "{%0,%1,%2,%3}, {%4,%5,%6,%7}, {%8,%9}, {%0,%1,%2,%3};"
        : "+f"(d[0]), "+f"(d[1]), "+f"(d[2]), "+f"(d[3])
        : "r"(a[0]), "r"(a[1]), "r"(a[2]), "r"(a[3]),
          "r"(b[0]), "r"(b[1]));
}

__device__ __forceinline__ void cpa16(float* s, const float* g) {
    uint32_t sa = (uint32_t)__cvta_generic_to_shared(s);
    asm volatile("cp.async.cg.shared.global [%0], [%1], 16;"
                 :: "r"(sa), "l"(g) : "memory");
}

// ---------------------------------------------------------------------------
// Pre-round pass: tf32-round x and all GEMM weights once.
// ---------------------------------------------------------------------------
#define RND_TOTAL4 ((XN + WQN + 2 * WKN + WON) / 4)   // 1703936 float4

__global__ __launch_bounds__(256) void round_pass(
    const float* __restrict__ x,
    const float* __restrict__ Wq, const float* __restrict__ Wk,
    const float* __restrict__ Wv, const float* __restrict__ Wo)
{
    int id = blockIdx.x * 256 + threadIdx.x;
    if (id >= RND_TOTAL4) return;
    int e = id * 4;
    const float* src;
    float* dst;
    if (e < XN)                        { src = x  + e;                    dst = g_Xr  + e; }
    else if ((e -= XN) < WQN)          { src = Wq + e;                    dst = g_Wqr + e; }
    else if ((e -= WQN) < WKN)         { src = Wk + e;                    dst = g_Wkr + e; }
    else if ((e -= WKN) < WKN)         { src = Wv + e;                    dst = g_Wvr + e; }
    else                               { src = Wo + (e - WKN);            dst = g_Wor + (e - WKN); }
    float4 v = *(const float4*)src;
    v.x = tf32r(v.x); v.y = tf32r(v.y); v.z = tf32r(v.z); v.w = tf32r(v.w);
    *(float4*)dst = v;
}

// ---------------------------------------------------------------------------
// tf32 mma.sync GEMM core:  C_tile = A[128,K] * B[128,K]^T
// Inputs pre-rounded to tf32. cp.async double-buffered smem.
// ---------------------------------------------------------------------------
#define LDS_S 36                  // 32 + 4 pad (words)
#define STG (128 * LDS_S)         // floats per stage per operand

__device__ __forceinline__ void gemm_body(
    const float* __restrict__ Ab, const float* __restrict__ Bp,
    float* __restrict__ Crow0, int N, int K, float* __restrict__ sm)
{
    float* smA = sm;              // 2 stages
    float* smB = sm + 2 * STG;

    const int tid = threadIdx.x;
    const int wid = tid >> 5;
    const int lane = tid & 31;
    const int warp_m = wid & 3;
    const int warp_n = wid >> 2;
    const int group = lane >> 2;
    const int kq = lane & 3;

    float acc[2][8][4];
#pragma unroll
    for (int mt = 0; mt < 2; mt++)
#pragma unroll
        for (int nt = 0; nt < 8; nt++)
#pragma unroll
            for (int c = 0; c < 4; c++) acc[mt][nt][c] = 0.f;

    const int nk = K >> 5;

#pragma unroll
    for (int t = 0; t < 4; t++) {
        int idx = tid + t * 256;
        int row = idx >> 3;
        int c4  = (idx & 7) << 2;
        cpa16(smA + row * LDS_S + c4, Ab + (size_t)row * K + c4);
        cpa16(smB + row * LDS_S + c4, Bp + (size_t)row * K + c4);
    }
    asm volatile("cp.async.commit_group;" ::: "memory");

    for (int kc = 0; kc < nk; kc++) {
        asm volatile("cp.async.wait_group 0;" ::: "memory");
        __syncthreads();

        if (kc + 1 < nk) {
            float* dA = smA + ((kc + 1) & 1) * STG;
            float* dB = smB + ((kc + 1) & 1) * STG;
            const int koff = (kc + 1) << 5;
#pragma unroll
            for (int t = 0; t < 4; t++) {
                int idx = tid + t * 256;
                int row = idx >> 3;
                int c4  = (idx & 7) << 2;
                cpa16(dA + row * LDS_S + c4, Ab + (size_t)row * K + koff + c4);
                cpa16(dB + row * LDS_S + c4, Bp + (size_t)row * K + koff + c4);
            }
            asm volatile("cp.async.commit_group;" ::: "memory");
        }

        const uint32_t* As = (const uint32_t*)(smA + (kc & 1) * STG);
        const uint32_t* Bs = (const uint32_t*)(smB + (kc & 1) * STG);
#pragma unroll
        for (int ks = 0; ks < 4; ks++) {
            const int k0 = ks * 8;
            uint32_t af[2][4];
#pragma unroll
            for (int mt = 0; mt < 2; mt++) {
                const uint32_t* ar = As + (warp_m * 32 + mt * 16 + group) * LDS_S + k0 + kq;
                af[mt][0] = ar[0];
                af[mt][1] = ar[8 * LDS_S];
                af[mt][2] = ar[4];
                af[mt][3] = ar[8 * LDS_S + 4];
            }
            uint32_t bf[8][2];
#pragma unroll
            for (int nt = 0; nt < 8; nt++) {
                const uint32_t* br = Bs + (warp_n * 64 + nt * 8 + group) * LDS_S + k0 + kq;
                bf[nt][0] = br[0];
                bf[nt][1] = br[4];
            }
#pragma unroll
            for (int mt = 0; mt < 2; mt++)
#pragma unroll
                for (int nt = 0; nt < 8; nt++)
                    mma_tf32(acc[mt][nt], af[mt], bf[nt]);
        }
    }

#pragma unroll
    for (int mt = 0; mt < 2; mt++) {
        int r = warp_m * 32 + mt * 16 + group;
#pragma unroll
        for (int nt = 0; nt < 8; nt++) {
            int cn = warp_n * 64 + nt * 8 + 2 * kq;
            *(float2*)(Crow0 + (size_t)r * N + cn) =
                make_float2(acc[mt][nt][0], acc[mt][nt][1]);
            *(float2*)(Crow0 + (size_t)(r + 8) * N + cn) =
                make_float2(acc[mt][nt][2], acc[mt][nt][3]);
        }
    }
}

// Merged QKV projection: grid.x 0..7 -> Q, 8..9 -> K, 10..11 -> V
__global__ __launch_bounds__(256, 2) void gemm_qkv(
    float* __restrict__ Qo, float* __restrict__ Ko, float* __restrict__ Vo)
{
    extern __shared__ float sm[];
    const int bx = blockIdx.x;
    const float* Bp;
    float* Cp;
    int N, nb;
    if (bx < 8)       { Bp = g_Wqr; Cp = Qo; N = QDIM;  nb = bx; }
    else if (bx < 10) { Bp = g_Wkr; Cp = Ko; N = KVDIM; nb = bx - 8; }
    else              { Bp = g_Wvr; Cp = Vo; N = KVDIM; nb = bx - 10; }
    gemm_body(g_Xr + (size_t)blockIdx.y * 128 * Cc,
              Bp + (size_t)nb * 128 * Cc,
              Cp + (size_t)blockIdx.y * 128 * N + nb * 128, N, Cc, sm);
}

__global__ __launch_bounds__(256, 2) void gemm_tc(
    const float* __restrict__ A, const float* __restrict__ B,
    float* __restrict__ C, int N, int K)
{
    extern __shared__ float sm[];
    gemm_body(A + (size_t)blockIdx.y * 128 * K,
              B + (size_t)blockIdx.x * 128 * K,
              C + (size_t)blockIdx.y * 128 * N + blockIdx.x * 128, N, K, sm);
}

// ---------------------------------------------------------------------------
// Postproc: per-token gate+V update, RoPE + RMS-norm on Q and K.
// Reads the ORIGINAL (unrounded) x for the gate.
// ---------------------------------------------------------------------------
__global__ __launch_bounds__(256) void postproc(
    const float* __restrict__ x, const float* __restrict__ ve,
    const float* __restrict__ cosb, const float* __restrict__ sinb,
    const float* __restrict__ Wg)
{
    const int row = blockIdx.x;
    const int t = row & (Tt - 1);
    const int warp = threadIdx.x >> 5;
    const int lane = threadIdx.x & 31;

    if (warp < HKV) {
        float p = 0.f;
        if (lane < GATE_CH)
            p = x[(size_t)row * Cc + lane] * Wg[warp * GATE_CH + lane];
#pragma unroll
        for (int o = 16; o > 0; o >>= 1)
            p += __shfl_xor_sync(0xffffffffu, p, o);
        float gate = 3.f / (1.f + __expf(-p));
        size_t base = (size_t)row * KVDIM + warp * Dd;
        g_V[base + lane]      += gate * ve[base + lane];
        g_V[base + 32 + lane] += gate * ve[base + 32 + lane];
    }

    const float cv = cosb[t * 32 + lane];
    const float sv = sinb[t * 32 + lane];
    for (int tsk = warp; tsk < Hh + HKV; tsk += 8) {
        float* ptr = (tsk < Hh)
            ? (g_Q + (size_t)row * QDIM + tsk * Dd)
            : (g_K + (size_t)row * KVDIM + (tsk - Hh) * Dd);
        float x1 = ptr[lane];
        float x2 = ptr[lane + 32];
        float y1 = x1 * cv + x2 * sv;
        float y2 = x2 * cv - x1 * sv;
        float ss = y1 * y1 + y2 * y2;
#pragma unroll
        for (int o = 16; o > 0; o >>= 1)
            ss += __shfl_xor_sync(0xffffffffu, ss, o);
        float sc = 1.2f * rsqrtf(ss * (1.0f / Dd) + 1.1920929e-7f);
        ptr[lane]      = y1 * sc;
        ptr[lane + 32] = y2 * sc;
    }
}

// ---------------------------------------------------------------------------
// mma.sync flash attention. CTA = (qtile64, kv-head g, batch b), covering all
// 4 GQA q-heads: M=256 score rows. Epilogue stores tf32-rounded Y.
// ---------------------------------------------------------------------------
#define SST 68   // smem row stride (floats)

__global__ __launch_bounds__(256, 1) void attn_mma(const int* __restrict__ wptr)
{
    extern __shared__ float dsm[];
    float* Ss = dsm;                        // [256][SST]
    float* Ks = dsm + 256 * SST;            // [64][SST]
    float* Vs = Ks + 64 * SST;              // [64][SST]

    const int qt = blockIdx.x, g = blockIdx.y, b = blockIdx.z;
    const int tid = threadIdx.x;
    const int wid = tid >> 5;
    const int lane = tid & 31;
    const int group = lane >> 2;
    const int kq = lane & 3;
    const int rbase = wid * 32;
    const int head = g * 4 + (wid >> 1);
    const int q0 = qt * 64;
    const int qloc0 = (wid & 1) * 32;

    uint32_t qf[2][8][4];
    {
        const float* Qb = g_Q + ((size_t)(b * Tt + q0)) * QDIM + head * Dd;
#pragma unroll
        for (int mt = 0; mt < 2; mt++) {
            int r0 = qloc0 + mt * 16 + group;
#pragma unroll
            for (int ks = 0; ks < 8; ks++) {
                int k0 = ks * 8 + kq;
                qf[mt][ks][0] = __float_as_uint(tf32r(Qb[(size_t)r0 * QDIM + k0]));
                qf[mt][ks][1] = __float_as_uint(tf32r(Qb[(size_t)(r0 + 8) * QDIM + k0]));
                qf[mt][ks][2] = __float_as_uint(tf32r(Qb[(size_t)r0 * QDIM + k0 + 4]));
                qf[mt][ks][3] = __float_as_uint(tf32r(Qb[(size_t)(r0 + 8) * QDIM + k0 + 4]));
            }
        }
    }

    float oacc[2][8][4];
#pragma unroll
    for (int mt = 0; mt < 2; mt++)
#pragma unroll
        for (int nt = 0; nt < 8; nt++)
#pragma unroll
            for (int c = 0; c < 4; c++) oacc[mt][nt][c] = 0.f;

    float mrow[2][2] = {{-1e30f, -1e30f}, {-1e30f, -1e30f}};
    float lrow[2][2] = {{0.f, 0.f}, {0.f, 0.f}};

    const int w = wptr[0];
    int jmin = q0 - w; if (jmin < 0) jmin = 0;

    for (int c0 = (jmin >> 6) << 6; c0 <= q0; c0 += 64) {
#pragma unroll
        for (int t = 0; t < 4; t++) {
            int idx = tid + t * 256;
            int key = idx >> 4;
            int d4  = (idx & 15) << 2;
            size_t src = ((size_t)(b * Tt + c0 + key)) * KVDIM + g * Dd + d4;
            float4 kv = *(const float4*)&g_K[src];
            float4 vv = *(const float4*)&g_V[src];
            float* kd = &Ks[key * SST + d4];
            kd[0] = tf32r(kv.x); kd[1] = tf32r(kv.y);
            kd[2] = tf32r(kv.z); kd[3] = tf32r(kv.w);
            float* vd = &Vs[key * SST + d4];
            vd[0] = tf32r(vv.x); vd[1] = tf32r(vv.y);
            vd[2] = tf32r(vv.z); vd[3] = tf32r(vv.w);
        }
        __syncthreads();

        float sacc[2][8][4];
#pragma unroll
        for (int mt = 0; mt < 2; mt++)
#pragma unroll
            for (int nt = 0; nt < 8; nt++)
#pragma unroll
                for (int c = 0; c < 4; c++) sacc[mt][nt][c] = 0.f;

#pragma unroll
        for (int ks = 0; ks < 8; ks++) {
            const int k0 = ks * 8;
            uint32_t bf[8][2];
#pragma unroll
            for (int nt = 0; nt < 8; nt++) {
                bf[nt][0] = __float_as_uint(Ks[(nt * 8 + group) * SST + k0 + kq]);
                bf[nt][1] = __float_as_uint(Ks[(nt * 8 + group) * SST + k0 + kq + 4]);
            }
#pragma unroll
            for (int mt = 0; mt < 2; mt++)
#pragma unroll
                for (int nt = 0; nt < 8; nt++)
                    mma_tf32(sacc[mt][nt], qf[mt][ks], bf[nt]);
        }

#pragma unroll
        for (int mt = 0; mt < 2; mt++) {
            const int i0 = q0 + qloc0 + mt * 16 + group;
            const int i1 = i0 + 8;
            float cmax0 = -1e30f, cmax1 = -1e30f;
#pragma unroll
            for (int nt = 0; nt < 8; nt++) {
                int jg = c0 + nt * 8 + 2 * kq;
                float s;
                s = (jg     <= i0 && (i0 - jg)     <= w) ? sacc[mt][nt][0] * 0.125f : -1e30f;
                sacc[mt][nt][0] = s; cmax0 = fmaxf(cmax0, s);
                s = (jg + 1 <= i0 && (i0 - jg - 1) <= w) ? sacc[mt][nt][1] * 0.125f : -1e30f;
                sacc[mt][nt][1] = s; cmax0 = fmaxf(cmax0, s);
                s = (jg     <= i1 && (i1 - jg)     <= w) ? sacc[mt][nt][2] * 0.125f : -1e30f;
                sacc[mt][nt][2] = s; cmax1 = fmaxf(cmax1, s);
                s = (jg + 1 <= i1 && (i1 - jg - 1) <= w) ? sacc[mt][nt][3] * 0.125f : -1e30f;
                sacc[mt][nt][3] = s; cmax1 = fmaxf(cmax1, s);
            }
            cmax0 = fmaxf(cmax0, __shfl_xor_sync(0xffffffffu, cmax0, 1));
            cmax0 = fmaxf(cmax0, __shfl_xor_sync(0xffffffffu, cmax0, 2));
            cmax1 = fmaxf(cmax1, __shfl_xor_sync(0xffffffffu, cmax1, 1));
            cmax1 = fmaxf(cmax1, __shfl_xor_sync(0xffffffffu, cmax1, 2));

            float mn0 = fmaxf(mrow[mt][0], cmax0);
            float mn1 = fmaxf(mrow[mt][1], cmax1);
            float r0 = __expf(mrow[mt][0] - mn0);
            float r1 = __expf(mrow[mt][1] - mn1);
            mrow[mt][0] = mn0; mrow[mt][1] = mn1;
            lrow[mt][0] *= r0; lrow[mt][1] *= r1;
#pragma unroll
            for (int nt = 0; nt < 8; nt++) {
                oacc[mt][nt][0] *= r0; oacc[mt][nt][1] *= r0;
                oacc[mt][nt][2] *= r1; oacc[mt][nt][3] *= r1;
            }
            const int prow0 = rbase + mt * 16 + group;
#pragma unroll
            for (int nt = 0; nt < 8; nt++) {
                float p0 = tf32r(__expf(sacc[mt][nt][0] - mn0));
                float p1 = tf32r(__expf(sacc[mt][nt][1] - mn0));
                float p2 = tf32r(__expf(sacc[mt][nt][2] - mn1));
                float p3 = tf32r(__expf(sacc[mt][nt][3] - mn1));
                lrow[mt][0] += p0 + p1;
                lrow[mt][1] += p2 + p3;
                *(float2*)&Ss[prow0 * SST + nt * 8 + 2 * kq] = make_float2(p0, p1);
                *(float2*)&Ss[(prow0 + 8) * SST + nt * 8 + 2 * kq] = make_float2(p2, p3);
            }
        }
        __syncwarp();

#pragma unroll
        for (int ks = 0; ks < 8; ks++) {
            const int k0 = ks * 8;
            uint32_t vf[8][2];
#pragma unroll
            for (int nt = 0; nt < 8; nt++) {
                vf[nt][0] = __float_as_uint(Vs[(k0 + kq) * SST + nt * 8 + group]);
                vf[nt][1] = __float_as_uint(Vs[(k0 + kq + 4) * SST + nt * 8 + group]);
            }
            uint32_t af[2][4];
#pragma unroll
            for (int mt = 0; mt < 2; mt++) {
                const int pr = rbase + mt * 16 + group;
                af[mt][0] = __float_as_uint(Ss[pr * SST + k0 + kq]);
                af[mt][1] = __float_as_uint(Ss[(pr + 8) * SST + k0 + kq]);
                af[mt][2] = __float_as_uint(Ss[pr * SST + k0 + kq + 4]);
                af[mt][3] = __float_as_uint(Ss[(pr + 8) * SST + k0 + kq + 4]);
            }
#pragma unroll
            for (int mt = 0; mt < 2; mt++)
#pragma unroll
                for (int nt = 0; nt < 8; nt++)
                    mma_tf32(oacc[mt][nt], af[mt], vf[nt]);
        }
        __syncthreads();
    }

    // finalize: store tf32-rounded so final GEMM reads pre-rounded A
#pragma unroll
    for (int mt = 0; mt < 2; mt++) {
        float l0 = lrow[mt][0], l1 = lrow[mt][1];
        l0 += __shfl_xor_sync(0xffffffffu, l0, 1);
        l0 += __shfl_xor_sync(0xffffffffu, l0, 2);
        l1 += __shfl_xor_sync(0xffffffffu, l1, 1);
        l1 += __shfl_xor_sync(0xffffffffu, l1, 2);
        float inv0 = 1.f / l0, inv1 = 1.f / l1;
        int r0 = q0 + qloc0 + mt * 16 + group;
        float* Y0 = g_Y + ((size_t)(b * Tt + r0)) * QDIM + head * Dd;
        float* Y1 = g_Y + ((size_t)(b * Tt + r0 + 8)) * QDIM + head * Dd;
#pragma unroll
        for (int nt = 0; nt < 8; nt++) {
            int cn = nt * 8 + 2 * kq;
            *(float2*)(Y0 + cn) = make_float2(tf32r(oacc[mt][nt][0] * inv0),
                                              tf32r(oacc[mt][nt][1] * inv0));
            *(float2*)(Y1 + cn) = make_float2(tf32r(oacc[mt][nt][2] * inv1),
                                              tf32r(oacc[mt][nt][3] * inv1));
        }
    }
}

// ---------------------------------------------------------------------------
extern "C" void kernel_launch(void* const* d_in, const int* in_sizes, int n_in,
                              void* d_out, int out_size)
{
    const float* x    = (const float*)d_in[0];
    const float* ve   = (const float*)d_in[1];
    const float* cosb = (const float*)d_in[2];
    const float* sinb = (const float*)d_in[3];
    const float* Wq   = (const float*)d_in[4];
    const float* Wk   = (const float*)d_in[5];
    const float* Wv   = (const float*)d_in[6];
    const float* Wo   = (const float*)d_in[7];
    const float* Wg   = (const float*)d_in[8];
    const int*   win  = (const int*)d_in[9];

    float* out = (float*)d_out;

    float* Qp; cudaGetSymbolAddress((void**)&Qp, g_Q);
    float* Kp; cudaGetSymbolAddress((void**)&Kp, g_K);
    float* Vp; cudaGetSymbolAddress((void**)&Vp, g_V);
    float* Yp; cudaGetSymbolAddress((void**)&Yp, g_Y);
    float* Wor; cudaGetSymbolAddress((void**)&Wor, g_Wor);

    const int GEMM_SMEM = 4 * STG * 4;   // 73728 bytes
    cudaFuncSetAttribute(gemm_qkv,
        cudaFuncAttributeMaxDynamicSharedMemorySize, GEMM_SMEM);
    cudaFuncSetAttribute(gemm_tc,
        cudaFuncAttributeMaxDynamicSharedMemorySize, GEMM_SMEM);
    cudaFuncSetAttribute(attn_mma,
        cudaFuncAttributeMaxDynamicSharedMemorySize, (256 + 128) * SST * 4);

    // pre-round x and weights to tf32
    round_pass<<<(RND_TOTAL4 + 255) / 256, 256>>>(x, Wq, Wk, Wv, Wo);

    // merged QKV projections (tf32 mma.sync)
    gemm_qkv<<<dim3(12, ROWS / 128), 256, GEMM_SMEM>>>(Qp, Kp, Vp);

    // gate + RoPE + RMS-norm
    postproc<<<ROWS, 256>>>(x, ve, cosb, sinb, Wg);

    // mma flash attention
    attn_mma<<<dim3(Tt / 64, HKV, Bb), 256, (256 + 128) * SST * 4>>>(win);

    // output projection
    gemm_tc<<<dim3(QDIM / 128, ROWS / 128), 256, GEMM_SMEM>>>(Yp, Wor, out, QDIM, Cc);
}